// round 1
// baseline (speedup 1.0000x reference)
#include <cuda_runtime.h>
#include <math.h>

#define BB 2
#define SS_ 2048
#define DD 1024
#define HH 16
#define HDIM 64
#define MLPD 4096
#define NROWS (BB*SS_)   // 4096
#define BHN (BB*HH)      // 32
#define LNEPS 1e-5f

// ---------------- scratch (static device globals; no allocs allowed) ----------
__device__ float g_h1[NROWS*DD];
__device__ float g_q [NROWS*DD];
__device__ float g_k [NROWS*DD];
__device__ float g_v [NROWS*DD];
__device__ float g_scores[(size_t)BHN*SS_*SS_];   // 536 MB
__device__ float g_attn[NROWS*DD];
__device__ float g_h2 [NROWS*DD];
__device__ float g_mlp[(size_t)NROWS*MLPD];       // 64 MB

// ---------------- helpers ----------------
__device__ __forceinline__ float warpSum(float v) {
    #pragma unroll
    for (int o = 16; o; o >>= 1) v += __shfl_xor_sync(0xffffffffu, v, o);
    return v;
}
__device__ __forceinline__ float warpMax(float v) {
    #pragma unroll
    for (int o = 16; o; o >>= 1) v = fmaxf(v, __shfl_xor_sync(0xffffffffu, v, o));
    return v;
}
__device__ __forceinline__ float gelu_exact(float x) {
    return 0.5f * x * (1.0f + erff(x * 0.70710678118654752f));
}

// ---------------- LayerNorm: one block per row of 1024 ----------------
__global__ void ln_kernel(const float* __restrict__ x, const float* __restrict__ g,
                          const float* __restrict__ b, float* __restrict__ out) {
    int row = blockIdx.x;
    int tid = threadIdx.x;            // 256
    const float4* xr = (const float4*)(x + (size_t)row * DD);
    float4 v = xr[tid];
    float s  = v.x + v.y + v.z + v.w;
    float sq = v.x*v.x + v.y*v.y + v.z*v.z + v.w*v.w;
    s  = warpSum(s);
    sq = warpSum(sq);
    __shared__ float shs[8], shq[8], shmv[2];
    int wid = tid >> 5, lane = tid & 31;
    if (lane == 0) { shs[wid] = s; shq[wid] = sq; }
    __syncthreads();
    if (wid == 0) {
        float a  = (lane < 8) ? shs[lane] : 0.f;
        float aq = (lane < 8) ? shq[lane] : 0.f;
        a  = warpSum(a);
        aq = warpSum(aq);
        if (lane == 0) {
            float mean = a * (1.0f / DD);
            float var  = aq * (1.0f / DD) - mean * mean;
            shmv[0] = mean;
            shmv[1] = rsqrtf(var + LNEPS);
        }
    }
    __syncthreads();
    float mean = shmv[0], inv = shmv[1];
    float4 gv = ((const float4*)g)[tid];
    float4 bv = ((const float4*)b)[tid];
    float4 o;
    o.x = (v.x - mean) * inv * gv.x + bv.x;
    o.y = (v.y - mean) * inv * gv.y + bv.y;
    o.z = (v.z - mean) * inv * gv.z + bv.z;
    o.w = (v.w - mean) * inv * gv.w + bv.w;
    ((float4*)(out + (size_t)row * DD))[tid] = o;
}

// ---------------- generic sgemm 128x128x8, 256 thr, 8x8/thread ----------------
// EPI: 0 = +bias ; 1 = +bias then gelu ; 2 = +bias +res (residual same shape as C)
template<int EPI>
__global__ void sgemm128(const float* __restrict__ A, const float* __restrict__ W,
                         const float* __restrict__ bias, const float* __restrict__ res,
                         float* __restrict__ C, int M, int N, int K) {
    __shared__ float As[8][128];
    __shared__ float Bs[8][128];
    int tid = threadIdx.x;
    int n0 = blockIdx.x * 128;
    int m0 = blockIdx.y * 128;
    int tx = tid & 15, ty = tid >> 4;

    int arow = tid >> 1;            // 0..127
    int acol = (tid & 1) * 4;       // 0 or 4
    int brow = tid >> 5;            // 0..7
    int bcol = (tid & 31) * 4;      // 0..124

    float acc[8][8];
    #pragma unroll
    for (int i = 0; i < 8; i++)
        #pragma unroll
        for (int j = 0; j < 8; j++) acc[i][j] = 0.f;

    for (int k0 = 0; k0 < K; k0 += 8) {
        float4 aReg = *(const float4*)(A + (size_t)(m0 + arow) * K + k0 + acol);
        float4 bReg = *(const float4*)(W + (size_t)(k0 + brow) * N + n0 + bcol);
        __syncthreads();
        As[acol + 0][arow] = aReg.x;
        As[acol + 1][arow] = aReg.y;
        As[acol + 2][arow] = aReg.z;
        As[acol + 3][arow] = aReg.w;
        *(float4*)&Bs[brow][bcol] = bReg;
        __syncthreads();
        #pragma unroll
        for (int kk = 0; kk < 8; kk++) {
            float a[8], b[8];
            #pragma unroll
            for (int i = 0; i < 8; i++) a[i] = As[kk][ty * 8 + i];
            #pragma unroll
            for (int j = 0; j < 8; j++) b[j] = Bs[kk][tx * 8 + j];
            #pragma unroll
            for (int i = 0; i < 8; i++)
                #pragma unroll
                for (int j = 0; j < 8; j++) acc[i][j] = fmaf(a[i], b[j], acc[i][j]);
        }
    }

    int row0 = m0 + ty * 8;
    int col0 = n0 + tx * 8;
    #pragma unroll
    for (int i = 0; i < 8; i++) {
        size_t rbase = (size_t)(row0 + i) * N;
        #pragma unroll
        for (int j = 0; j < 8; j++) {
            float c = acc[i][j] + bias[col0 + j];
            if (EPI == 1) c = gelu_exact(c);
            if (EPI == 2) c += res[rbase + col0 + j];
            C[rbase + col0 + j] = c;
        }
    }
}

// ---------------- attention scores: S = scale*Q K^T + dis + cls ----------------
// per (bh, t-tile, s-tile): 64x64 output, K=64 fully resident
__global__ void scores_kernel(const float* __restrict__ q, const float* __restrict__ k,
                              const float* __restrict__ dism, const float* __restrict__ clsm,
                              float* __restrict__ scores) {
    int bh = blockIdx.x;                  // 0..31  (fastest -> mask tiles shared in L2)
    int t0 = blockIdx.y * 64;
    int s0 = blockIdx.z * 64;
    int b  = bh / HH;
    const float* Q = q + (size_t)bh * SS_ * HDIM;
    const float* Kp = k + (size_t)bh * SS_ * HDIM;

    __shared__ float Qs[64][65];
    __shared__ float Ks[64][65];
    int tid = threadIdx.x;                // 256
    for (int idx = tid; idx < 64 * 16; idx += 256) {
        int row = idx >> 4;
        int c4  = (idx & 15) * 4;
        float4 vq = *(const float4*)(Q  + (size_t)(s0 + row) * HDIM + c4);
        float4 vk = *(const float4*)(Kp + (size_t)(t0 + row) * HDIM + c4);
        Qs[row][c4+0] = vq.x; Qs[row][c4+1] = vq.y; Qs[row][c4+2] = vq.z; Qs[row][c4+3] = vq.w;
        Ks[row][c4+0] = vk.x; Ks[row][c4+1] = vk.y; Ks[row][c4+2] = vk.z; Ks[row][c4+3] = vk.w;
    }
    __syncthreads();

    int tx = tid & 15, ty = tid >> 4;
    float acc[4][4];
    #pragma unroll
    for (int i = 0; i < 4; i++)
        #pragma unroll
        for (int j = 0; j < 4; j++) acc[i][j] = 0.f;

    #pragma unroll 8
    for (int kk = 0; kk < 64; kk++) {
        float a[4], bb[4];
        #pragma unroll
        for (int i = 0; i < 4; i++) a[i]  = Qs[ty * 4 + i][kk];
        #pragma unroll
        for (int j = 0; j < 4; j++) bb[j] = Ks[tx * 4 + j][kk];
        #pragma unroll
        for (int i = 0; i < 4; i++)
            #pragma unroll
            for (int j = 0; j < 4; j++) acc[i][j] = fmaf(a[i], bb[j], acc[i][j]);
    }

    const float scale = 0.125f;           // 1/sqrt(64)
    size_t mbase = (size_t)b  * SS_ * SS_;
    size_t sbase = (size_t)bh * SS_ * SS_;
    #pragma unroll
    for (int i = 0; i < 4; i++) {
        int s = s0 + ty * 4 + i;
        size_t mrow = mbase + (size_t)s * SS_;
        size_t srow = sbase + (size_t)s * SS_;
        #pragma unroll
        for (int j = 0; j < 4; j++) {
            int t = t0 + tx * 4 + j;
            float m = dism[mrow + t] + clsm[mrow + t];
            scores[srow + t] = acc[i][j] * scale + m;
        }
    }
}

// ---------------- softmax over rows of 2048, in-register one pass -------------
__global__ void softmax_kernel(float* __restrict__ scores) {
    float* r = scores + (size_t)blockIdx.x * SS_;
    int tid = threadIdx.x;                // 256; 8 floats/thread
    float4 v0 = ((float4*)r)[tid];
    float4 v1 = ((float4*)r)[tid + 256];
    float m = fmaxf(fmaxf(fmaxf(v0.x, v0.y), fmaxf(v0.z, v0.w)),
                    fmaxf(fmaxf(v1.x, v1.y), fmaxf(v1.z, v1.w)));
    m = warpMax(m);
    __shared__ float sh[8], shv[1];
    int wid = tid >> 5, lane = tid & 31;
    if (lane == 0) sh[wid] = m;
    __syncthreads();
    if (wid == 0) {
        float a = (lane < 8) ? sh[lane] : -1e30f;
        a = warpMax(a);
        if (lane == 0) shv[0] = a;
    }
    __syncthreads();
    m = shv[0];
    v0.x = __expf(v0.x - m); v0.y = __expf(v0.y - m); v0.z = __expf(v0.z - m); v0.w = __expf(v0.w - m);
    v1.x = __expf(v1.x - m); v1.y = __expf(v1.y - m); v1.z = __expf(v1.z - m); v1.w = __expf(v1.w - m);
    float s = v0.x + v0.y + v0.z + v0.w + v1.x + v1.y + v1.z + v1.w;
    s = warpSum(s);
    if (lane == 0) sh[wid] = s;
    __syncthreads();
    if (wid == 0) {
        float a = (lane < 8) ? sh[lane] : 0.f;
        a = warpSum(a);
        if (lane == 0) shv[0] = a;
    }
    __syncthreads();
    float inv = 1.0f / shv[0];
    v0.x *= inv; v0.y *= inv; v0.z *= inv; v0.w *= inv;
    v1.x *= inv; v1.y *= inv; v1.z *= inv; v1.w *= inv;
    ((float4*)r)[tid] = v0;
    ((float4*)r)[tid + 256] = v1;
}

// ---------------- PV: O = P @ V  (+ residual x), per bh -----------------------
// M=2048, N=64, K=2048 ; BM=128, BN=64, BK=16 ; 256 thr, 8x4/thread
__global__ void pv_kernel(const float* __restrict__ scores, const float* __restrict__ v,
                          const float* __restrict__ x, float* __restrict__ out) {
    int bh = blockIdx.x;
    int m0 = blockIdx.y * 128;
    size_t sbase = (size_t)bh * SS_ * SS_;
    const float* V = v + (size_t)bh * SS_ * HDIM;

    __shared__ float Pst[16][128];  // [k][m]
    __shared__ float Vs[16][64];    // [k][n]
    int tid = threadIdx.x;
    int tx = tid & 15, ty = tid >> 4;

    float acc[8][4];
    #pragma unroll
    for (int i = 0; i < 8; i++)
        #pragma unroll
        for (int j = 0; j < 4; j++) acc[i][j] = 0.f;

    int vrow = tid >> 4;            // 0..15
    int vc4  = (tid & 15) * 4;      // 0..60

    for (int k0 = 0; k0 < SS_; k0 += 16) {
        float4 p0, p1, vv;
        {
            int fid0 = tid;         // 0..255
            int fid1 = tid + 256;   // 256..511
            int r0 = fid0 >> 2, c0 = (fid0 & 3) * 4;
            int r1 = fid1 >> 2, c1 = (fid1 & 3) * 4;
            p0 = *(const float4*)(scores + sbase + (size_t)(m0 + r0) * SS_ + k0 + c0);
            p1 = *(const float4*)(scores + sbase + (size_t)(m0 + r1) * SS_ + k0 + c1);
            vv = *(const float4*)(V + (size_t)(k0 + vrow) * HDIM + vc4);
            __syncthreads();
            Pst[c0+0][r0] = p0.x; Pst[c0+1][r0] = p0.y; Pst[c0+2][r0] = p0.z; Pst[c0+3][r0] = p0.w;
            Pst[c1+0][r1] = p1.x; Pst[c1+1][r1] = p1.y; Pst[c1+2][r1] = p1.z; Pst[c1+3][r1] = p1.w;
            *(float4*)&Vs[vrow][vc4] = vv;
        }
        __syncthreads();
        #pragma unroll
        for (int kk = 0; kk < 16; kk++) {
            float a[8], b[4];
            #pragma unroll
            for (int i = 0; i < 8; i++) a[i] = Pst[kk][ty * 8 + i];
            #pragma unroll
            for (int j = 0; j < 4; j++) b[j] = Vs[kk][tx * 4 + j];
            #pragma unroll
            for (int i = 0; i < 8; i++)
                #pragma unroll
                for (int j = 0; j < 4; j++) acc[i][j] = fmaf(a[i], b[j], acc[i][j]);
        }
    }

    size_t obase = (size_t)bh * SS_ * HDIM;
    #pragma unroll
    for (int i = 0; i < 8; i++) {
        int s = m0 + ty * 8 + i;
        size_t rbase = obase + (size_t)s * HDIM;
        #pragma unroll
        for (int j = 0; j < 4; j++) {
            int hd = tx * 4 + j;
            out[rbase + hd] = acc[i][j] + x[rbase + hd];   // residual (flat layouts identical)
        }
    }
}

// ---------------- launch ------------------------------------------------------
extern "C" void kernel_launch(void* const* d_in, const int* in_sizes, int n_in,
                              void* d_out, int out_size) {
    const float* x    = (const float*)d_in[0];
    const float* dism = (const float*)d_in[1];
    const float* clsm = (const float*)d_in[2];
    const float* wq   = (const float*)d_in[3];
    const float* bq   = (const float*)d_in[4];
    const float* wk   = (const float*)d_in[5];
    const float* bk   = (const float*)d_in[6];
    const float* wv   = (const float*)d_in[7];
    const float* bv   = (const float*)d_in[8];
    const float* ln1g = (const float*)d_in[9];
    const float* ln1b = (const float*)d_in[10];
    const float* ln2g = (const float*)d_in[11];
    const float* ln2b = (const float*)d_in[12];
    const float* w1   = (const float*)d_in[13];
    const float* b1   = (const float*)d_in[14];
    const float* w2   = (const float*)d_in[15];
    const float* b2   = (const float*)d_in[16];
    float* out = (float*)d_out;

    float *h1, *q, *k, *v, *sc, *attn, *h2, *mlp;
    cudaGetSymbolAddress((void**)&h1,   g_h1);
    cudaGetSymbolAddress((void**)&q,    g_q);
    cudaGetSymbolAddress((void**)&k,    g_k);
    cudaGetSymbolAddress((void**)&v,    g_v);
    cudaGetSymbolAddress((void**)&sc,   g_scores);
    cudaGetSymbolAddress((void**)&attn, g_attn);
    cudaGetSymbolAddress((void**)&h2,   g_h2);
    cudaGetSymbolAddress((void**)&mlp,  g_mlp);

    // LN1
    ln_kernel<<<NROWS, 256>>>(x, ln1g, ln1b, h1);

    // QKV projections
    dim3 gqkv(DD / 128, NROWS / 128);
    sgemm128<0><<<gqkv, 256>>>(h1, wq, bq, nullptr, q, NROWS, DD, DD);
    sgemm128<0><<<gqkv, 256>>>(h1, wk, bk, nullptr, k, NROWS, DD, DD);
    sgemm128<0><<<gqkv, 256>>>(h1, wv, bv, nullptr, v, NROWS, DD, DD);

    // scores = scale * Q K^T + masks
    dim3 gsc(BHN, SS_ / 64, SS_ / 64);
    scores_kernel<<<gsc, 256>>>(q, k, dism, clsm, sc);

    // softmax rows
    softmax_kernel<<<BHN * SS_, 256>>>(sc);

    // O = P V  + residual x
    dim3 gpv(BHN, SS_ / 128);
    pv_kernel<<<gpv, 256>>>(sc, v, x, attn);

    // LN2
    ln_kernel<<<NROWS, 256>>>(attn, ln2g, ln2b, h2);

    // MLP
    dim3 g1(MLPD / 128, NROWS / 128);
    sgemm128<1><<<g1, 256>>>(h2, w1, b1, nullptr, mlp, NROWS, MLPD, DD);
    dim3 g2(DD / 128, NROWS / 128);
    sgemm128<2><<<g2, 256>>>(mlp, w2, b2, h2, out, NROWS, DD, MLPD);
}

// round 2
// speedup vs baseline: 2.5824x; 2.5824x over previous
#include <cuda_runtime.h>
#include <math.h>
#include <stdint.h>

#define BB 2
#define SS_ 2048
#define DD 1024
#define HH 16
#define HDIM 64
#define MLPD 4096
#define NROWS (BB*SS_)   // 4096
#define BHN (BB*HH)      // 32
#define LNEPS 1e-5f

// ---------------- scratch (static device globals; no allocs allowed) ----------
__device__ float g_h1[NROWS*DD];
__device__ float g_q [NROWS*DD];
__device__ float g_k [NROWS*DD];
__device__ float g_v [NROWS*DD];
__device__ float g_scores[(size_t)BHN*SS_*SS_];   // 536 MB
__device__ float g_attn[NROWS*DD];
__device__ float g_h2 [NROWS*DD];
__device__ float g_mlp[(size_t)NROWS*MLPD];       // 64 MB
__device__ float g_cm [(size_t)BB*SS_*SS_];       // combined mask, 33.5 MB

// ---------------- helpers ----------------
__device__ __forceinline__ float warpSum(float v) {
    #pragma unroll
    for (int o = 16; o; o >>= 1) v += __shfl_xor_sync(0xffffffffu, v, o);
    return v;
}
__device__ __forceinline__ float warpMax(float v) {
    #pragma unroll
    for (int o = 16; o; o >>= 1) v = fmaxf(v, __shfl_xor_sync(0xffffffffu, v, o));
    return v;
}
__device__ __forceinline__ float gelu_exact(float x) {
    return 0.5f * x * (1.0f + erff(x * 0.70710678118654752f));
}
__device__ __forceinline__ uint32_t f2tf(float f) {
    uint32_t u;
    asm("cvt.rna.tf32.f32 %0, %1;" : "=r"(u) : "f"(f));
    return u;
}
__device__ __forceinline__ void mma_tf32(float* c, const uint32_t* a, const uint32_t* b) {
    asm volatile(
        "mma.sync.aligned.m16n8k8.row.col.f32.tf32.tf32.f32 "
        "{%0,%1,%2,%3},{%4,%5,%6,%7},{%8,%9},{%0,%1,%2,%3};"
        : "+f"(c[0]), "+f"(c[1]), "+f"(c[2]), "+f"(c[3])
        : "r"(a[0]), "r"(a[1]), "r"(a[2]), "r"(a[3]), "r"(b[0]), "r"(b[1]));
}
__device__ __forceinline__ void cpa16(float* dst, const float* src) {
    uint32_t d = (uint32_t)__cvta_generic_to_shared(dst);
    asm volatile("cp.async.cg.shared.global [%0],[%1],16;" :: "r"(d), "l"(src));
}

// ---------------- LayerNorm: one block per row of 1024 ----------------
__global__ void ln_kernel(const float* __restrict__ x, const float* __restrict__ g,
                          const float* __restrict__ b, float* __restrict__ out) {
    int row = blockIdx.x;
    int tid = threadIdx.x;            // 256
    const float4* xr = (const float4*)(x + (size_t)row * DD);
    float4 v = xr[tid];
    float s  = v.x + v.y + v.z + v.w;
    float sq = v.x*v.x + v.y*v.y + v.z*v.z + v.w*v.w;
    s  = warpSum(s);
    sq = warpSum(sq);
    __shared__ float shs[8], shq[8], shmv[2];
    int wid = tid >> 5, lane = tid & 31;
    if (lane == 0) { shs[wid] = s; shq[wid] = sq; }
    __syncthreads();
    if (wid == 0) {
        float a  = (lane < 8) ? shs[lane] : 0.f;
        float aq = (lane < 8) ? shq[lane] : 0.f;
        a  = warpSum(a);
        aq = warpSum(aq);
        if (lane == 0) {
            float mean = a * (1.0f / DD);
            float var  = aq * (1.0f / DD) - mean * mean;
            shmv[0] = mean;
            shmv[1] = rsqrtf(var + LNEPS);
        }
    }
    __syncthreads();
    float mean = shmv[0], inv = shmv[1];
    float4 gv = ((const float4*)g)[tid];
    float4 bv = ((const float4*)b)[tid];
    float4 o;
    o.x = (v.x - mean) * inv * gv.x + bv.x;
    o.y = (v.y - mean) * inv * gv.y + bv.y;
    o.z = (v.z - mean) * inv * gv.z + bv.z;
    o.w = (v.w - mean) * inv * gv.w + bv.w;
    ((float4*)(out + (size_t)row * DD))[tid] = o;
}

// ---------------- combined mask ----------------
__global__ void cm_kernel(const float* __restrict__ a, const float* __restrict__ b,
                          float* __restrict__ o, int n4) {
    int i = blockIdx.x * blockDim.x + threadIdx.x;
    if (i < n4) {
        float4 x = ((const float4*)a)[i];
        float4 y = ((const float4*)b)[i];
        float4 z;
        z.x = x.x + y.x; z.y = x.y + y.y; z.z = x.z + y.z; z.w = x.w + y.w;
        ((float4*)o)[i] = z;
    }
}

// ---------------- tf32 tensor-core GEMM -----------------------------
// C[M,N] = A[M,K] @ B  (+ epilogue).  BM=128, BK=16, BN in {128, 64}.
// TRANSB: B given as row-major [N,K] (used for Q K^T).
// EPI: 0 = +bias ; 1 = +bias,gelu ; 2 = +bias,+res ; 3 = scale*acc + cm ; 4 = +res
// BATCHX: batch index on blockIdx.x (heads share mask tiles in L2).
template<int EPI, bool TRANSB, int BN, bool BATCHX>
__global__ void tgemm(const float* __restrict__ A, const float* __restrict__ Bm,
                      const float* __restrict__ bias, const float* __restrict__ res,
                      const float* __restrict__ cm,
                      float* __restrict__ C, int M, int N, int K,
                      size_t sA, size_t sB, size_t sC) {
    static_assert(BN == 128 || BN == 64, "BN");
    static_assert(!TRANSB || BN == 128, "transB assumes BN=128");
    constexpr int BK   = 16;
    constexpr int ASTR = BK + 4;                       // 20
    constexpr int BSTR = TRANSB ? (BK + 4) : (BN + 4);
    constexpr int BSZ  = TRANSB ? BN * (BK + 4) : BK * (BN + 4);
    constexpr int WN   = (BN == 128) ? 2 : 1;          // warps along N
    constexpr int WM   = 8 / WN;                       // 4 or 8
    constexpr int MM   = (128 / WM) / 16;              // 2 or 1
    constexpr int NN   = (BN / WN) / 8;                // 8

    __shared__ float As[2][128 * ASTR];
    __shared__ float Bs[2][BSZ];

    int tid = threadIdx.x;
    int batch, n0, m0;
    if (BATCHX) { batch = blockIdx.x; n0 = blockIdx.y * BN; m0 = blockIdx.z * 128; }
    else        { batch = blockIdx.z; n0 = blockIdx.x * BN; m0 = blockIdx.y * 128; }

    const float* Ab = A + (size_t)batch * sA;
    const float* Bb = Bm + (size_t)batch * sB;
    float*       Cb = C + (size_t)batch * sC;
    const float* Rb = (EPI == 2 || EPI == 4) ? res + ((EPI == 4) ? (size_t)batch * sC : 0) : nullptr;
    const float* cmb = (EPI == 3) ? cm + (size_t)(batch / HH) * (size_t)SS_ * SS_ : nullptr;

    int ldA = K;
    int ldB = TRANSB ? K : N;

    int wid = tid >> 5, lane = tid & 31;
    int g = lane >> 2, t4 = lane & 3;
    int wm = (wid % WM) * (128 / WM);
    int wn = (wid / WM) * (BN / WN);

    float acc[MM][NN][4];
    #pragma unroll
    for (int i = 0; i < MM; i++)
        #pragma unroll
        for (int j = 0; j < NN; j++)
            #pragma unroll
            for (int q = 0; q < 4; q++) acc[i][j][q] = 0.f;

    auto load_tiles = [&](int buf, int k0) {
        #pragma unroll
        for (int s = 0; s < 2; s++) {
            int idx = tid + s * 256;                   // 512 chunks
            int row = idx >> 2, c4 = (idx & 3) * 4;
            cpa16(&As[buf][row * ASTR + c4], Ab + (size_t)(m0 + row) * ldA + k0 + c4);
        }
        if (TRANSB) {
            #pragma unroll
            for (int s = 0; s < 2; s++) {
                int idx = tid + s * 256;
                int row = idx >> 2, c4 = (idx & 3) * 4;
                cpa16(&Bs[buf][row * BSTR + c4], Bb + (size_t)(n0 + row) * ldB + k0 + c4);
            }
        } else {
            constexpr int CH = BN / 4;
            constexpr int TOT = BK * CH;               // 512 or 256
            #pragma unroll
            for (int s = 0; s < TOT / 256; s++) {
                int idx = tid + s * 256;
                int row = idx / CH, c4 = (idx % CH) * 4;
                cpa16(&Bs[buf][row * BSTR + c4], Bb + (size_t)(k0 + row) * ldB + n0 + c4);
            }
        }
        asm volatile("cp.async.commit_group;");
    };

    auto compute = [&](int buf) {
        #pragma unroll
        for (int ks = 0; ks < 2; ks++) {
            int kk = ks * 8;
            uint32_t af[MM][4];
            #pragma unroll
            for (int i = 0; i < MM; i++) {
                int r = wm + i * 16 + g;
                af[i][0] = f2tf(As[buf][(r    ) * ASTR + kk + t4]);
                af[i][1] = f2tf(As[buf][(r + 8) * ASTR + kk + t4]);
                af[i][2] = f2tf(As[buf][(r    ) * ASTR + kk + t4 + 4]);
                af[i][3] = f2tf(As[buf][(r + 8) * ASTR + kk + t4 + 4]);
            }
            uint32_t bf[NN][2];
            #pragma unroll
            for (int j = 0; j < NN; j++) {
                int c = wn + j * 8 + g;
                if (TRANSB) {
                    bf[j][0] = f2tf(Bs[buf][c * BSTR + kk + t4]);
                    bf[j][1] = f2tf(Bs[buf][c * BSTR + kk + t4 + 4]);
                } else {
                    bf[j][0] = f2tf(Bs[buf][(kk + t4    ) * BSTR + c]);
                    bf[j][1] = f2tf(Bs[buf][(kk + t4 + 4) * BSTR + c]);
                }
            }
            #pragma unroll
            for (int i = 0; i < MM; i++)
                #pragma unroll
                for (int j = 0; j < NN; j++)
                    mma_tf32(acc[i][j], af[i], bf[j]);
        }
    };

    int nk = K / BK;
    load_tiles(0, 0);
    for (int it = 0; it < nk; it++) {
        if (it + 1 < nk) load_tiles((it + 1) & 1, (it + 1) * BK);
        if (it + 1 < nk) asm volatile("cp.async.wait_group 1;");
        else             asm volatile("cp.async.wait_group 0;");
        __syncthreads();
        compute(it & 1);
        __syncthreads();
    }

    // epilogue
    #pragma unroll
    for (int i = 0; i < MM; i++) {
        int r0 = m0 + wm + i * 16 + g;
        #pragma unroll
        for (int j = 0; j < NN; j++) {
            int c = n0 + wn + j * 8 + t4 * 2;
            float v0 = acc[i][j][0], v1 = acc[i][j][1];
            float v2 = acc[i][j][2], v3 = acc[i][j][3];
            size_t o0 = (size_t)r0 * N + c;
            size_t o1 = (size_t)(r0 + 8) * N + c;
            if (EPI <= 2) {
                float b0 = bias[c], b1 = bias[c + 1];
                v0 += b0; v1 += b1; v2 += b0; v3 += b1;
            }
            if (EPI == 1) {
                v0 = gelu_exact(v0); v1 = gelu_exact(v1);
                v2 = gelu_exact(v2); v3 = gelu_exact(v3);
            }
            if (EPI == 2 || EPI == 4) {
                float2 r0v = *(const float2*)&Rb[o0];
                float2 r1v = *(const float2*)&Rb[o1];
                v0 += r0v.x; v1 += r0v.y; v2 += r1v.x; v3 += r1v.y;
            }
            if (EPI == 3) {
                const float scale = 0.125f;            // 1/sqrt(64)
                float2 m0v = *(const float2*)&cmb[o0];
                float2 m1v = *(const float2*)&cmb[o1];
                v0 = v0 * scale + m0v.x; v1 = v1 * scale + m0v.y;
                v2 = v2 * scale + m1v.x; v3 = v3 * scale + m1v.y;
            }
            float2 w0; w0.x = v0; w0.y = v1;
            float2 w1; w1.x = v2; w1.y = v3;
            *(float2*)&Cb[o0] = w0;
            *(float2*)&Cb[o1] = w1;
        }
    }
}

// ---------------- softmax over rows of 2048, in-register one pass -------------
__global__ void softmax_kernel(float* __restrict__ scores) {
    float* r = scores + (size_t)blockIdx.x * SS_;
    int tid = threadIdx.x;                // 256; 8 floats/thread
    float4 v0 = ((float4*)r)[tid];
    float4 v1 = ((float4*)r)[tid + 256];
    float m = fmaxf(fmaxf(fmaxf(v0.x, v0.y), fmaxf(v0.z, v0.w)),
                    fmaxf(fmaxf(v1.x, v1.y), fmaxf(v1.z, v1.w)));
    m = warpMax(m);
    __shared__ float sh[8], shv[1];
    int wid = tid >> 5, lane = tid & 31;
    if (lane == 0) sh[wid] = m;
    __syncthreads();
    if (wid == 0) {
        float a = (lane < 8) ? sh[lane] : -1e30f;
        a = warpMax(a);
        if (lane == 0) shv[0] = a;
    }
    __syncthreads();
    m = shv[0];
    v0.x = __expf(v0.x - m); v0.y = __expf(v0.y - m); v0.z = __expf(v0.z - m); v0.w = __expf(v0.w - m);
    v1.x = __expf(v1.x - m); v1.y = __expf(v1.y - m); v1.z = __expf(v1.z - m); v1.w = __expf(v1.w - m);
    float s = v0.x + v0.y + v0.z + v0.w + v1.x + v1.y + v1.z + v1.w;
    s = warpSum(s);
    if (lane == 0) sh[wid] = s;
    __syncthreads();
    if (wid == 0) {
        float a = (lane < 8) ? sh[lane] : 0.f;
        a = warpSum(a);
        if (lane == 0) shv[0] = a;
    }
    __syncthreads();
    float inv = 1.0f / shv[0];
    v0.x *= inv; v0.y *= inv; v0.z *= inv; v0.w *= inv;
    v1.x *= inv; v1.y *= inv; v1.z *= inv; v1.w *= inv;
    ((float4*)r)[tid] = v0;
    ((float4*)r)[tid + 256] = v1;
}

// ---------------- launch ------------------------------------------------------
extern "C" void kernel_launch(void* const* d_in, const int* in_sizes, int n_in,
                              void* d_out, int out_size) {
    const float* x    = (const float*)d_in[0];
    const float* dism = (const float*)d_in[1];
    const float* clsm = (const float*)d_in[2];
    const float* wq   = (const float*)d_in[3];
    const float* bq   = (const float*)d_in[4];
    const float* wk   = (const float*)d_in[5];
    const float* bk   = (const float*)d_in[6];
    const float* wv   = (const float*)d_in[7];
    const float* bv   = (const float*)d_in[8];
    const float* ln1g = (const float*)d_in[9];
    const float* ln1b = (const float*)d_in[10];
    const float* ln2g = (const float*)d_in[11];
    const float* ln2b = (const float*)d_in[12];
    const float* w1   = (const float*)d_in[13];
    const float* b1   = (const float*)d_in[14];
    const float* w2   = (const float*)d_in[15];
    const float* b2   = (const float*)d_in[16];
    float* out = (float*)d_out;

    float *h1, *q, *k, *v, *sc, *attn, *h2, *mlp, *cm;
    cudaGetSymbolAddress((void**)&h1,   g_h1);
    cudaGetSymbolAddress((void**)&q,    g_q);
    cudaGetSymbolAddress((void**)&k,    g_k);
    cudaGetSymbolAddress((void**)&v,    g_v);
    cudaGetSymbolAddress((void**)&sc,   g_scores);
    cudaGetSymbolAddress((void**)&attn, g_attn);
    cudaGetSymbolAddress((void**)&h2,   g_h2);
    cudaGetSymbolAddress((void**)&mlp,  g_mlp);
    cudaGetSymbolAddress((void**)&cm,   g_cm);

    // LN1 + combined mask
    ln_kernel<<<NROWS, 256>>>(x, ln1g, ln1b, h1);
    cm_kernel<<<(BB * SS_ * SS_ / 4 + 255) / 256, 256>>>(dism, clsm, cm, BB * SS_ * SS_ / 4);

    // QKV projections (tf32 tensor cores)
    dim3 gqkv(DD / 128, NROWS / 128, 1);
    tgemm<0, false, 128, false><<<gqkv, 256>>>(h1, wq, bq, nullptr, nullptr, q, NROWS, DD, DD, 0, 0, 0);
    tgemm<0, false, 128, false><<<gqkv, 256>>>(h1, wk, bk, nullptr, nullptr, k, NROWS, DD, DD, 0, 0, 0);
    tgemm<0, false, 128, false><<<gqkv, 256>>>(h1, wv, bv, nullptr, nullptr, v, NROWS, DD, DD, 0, 0, 0);

    // scores = scale * Q K^T + cm   (batched over 32 heads on blockIdx.x)
    dim3 gsc(BHN, SS_ / 128, SS_ / 128);
    tgemm<3, true, 128, true><<<gsc, 256>>>(q, k, nullptr, nullptr, cm, sc,
                                            SS_, SS_, HDIM,
                                            (size_t)SS_ * HDIM, (size_t)SS_ * HDIM, (size_t)SS_ * SS_);

    // softmax rows
    softmax_kernel<<<BHN * SS_, 256>>>(sc);

    // O = P V + residual x
    dim3 gpv(1, SS_ / 128, BHN);
    tgemm<4, false, 64, false><<<gpv, 256>>>(sc, v, nullptr, x, nullptr, attn,
                                             SS_, HDIM, SS_,
                                             (size_t)SS_ * SS_, (size_t)SS_ * HDIM, (size_t)SS_ * HDIM);

    // LN2
    ln_kernel<<<NROWS, 256>>>(attn, ln2g, ln2b, h2);

    // MLP
    dim3 g1(MLPD / 128, NROWS / 128, 1);
    tgemm<1, false, 128, false><<<g1, 256>>>(h2, w1, b1, nullptr, nullptr, mlp, NROWS, MLPD, DD, 0, 0, 0);
    dim3 g2(DD / 128, NROWS / 128, 1);
    tgemm<2, false, 128, false><<<g2, 256>>>(mlp, w2, b2, h2, nullptr, out, NROWS, DD, MLPD, 0, 0, 0);
}